// round 13
// baseline (speedup 1.0000x reference)
#include <cuda_runtime.h>
#include <math_constants.h>
#include <cstdint>

typedef unsigned long long ULL;

#define Bc 1024
#define Sc 2048
#define Hc 50
#define TT 128
#define NTILE 16
#define NTH 256
#define RS 60
#define L2E 1.4426950408889634f

// ---- dynamic SMEM layout (bytes) ----
#define OFF_BUF0  0                // float[128*60]  30720
#define OFF_BUF1  30720            // float[128*60]  30720 (transient bfrag at setup)
#define OFF_WS    61440            // float[64]
#define OFF_PPV   61696            // float[64]
#define OFF_SPART 61952            // float[2*128]   1024
#define OFF_MBITS 62976            // uint32[64]      256
#define OFF_SL    63232            // float[8]         32
#define OFF_SCTX  63264            // ULL[8][25]     1600
#define SMEM_BYTES 64864

__device__ __forceinline__ uint32_t smem_u32(const void* p) {
    uint32_t a;
    asm("{ .reg .u64 t; cvta.to.shared.u64 t, %1; cvt.u32.u64 %0, t; }" : "=r"(a) : "l"(p));
    return a;
}
__device__ __forceinline__ float fast_ex2(float x) {
    float r; asm("ex2.approx.f32 %0, %1;" : "=f"(r) : "f"(x)); return r;
}
__device__ __forceinline__ float fast_tanh(float x) {
    float r; asm("tanh.approx.f32 %0, %1;" : "=f"(r) : "f"(x)); return r;
}
__device__ __forceinline__ ULL pack2(float lo, float hi) {
    ULL r; asm("mov.b64 %0, {%1, %2};" : "=l"(r) : "f"(lo), "f"(hi)); return r;
}
__device__ __forceinline__ void unpack2(ULL v, float& lo, float& hi) {
    asm("mov.b64 {%0, %1}, %2;" : "=f"(lo), "=f"(hi) : "l"(v));
}
#define FMA2(d, a, b) asm("fma.rn.f32x2 %0, %1, %2, %0;" : "+l"(d) : "l"(a), "l"(b))
__device__ __forceinline__ ULL add2(ULL a, ULL b) {
    ULL r; asm("add.rn.f32x2 %0, %1, %2;" : "=l"(r) : "l"(a), "l"(b)); return r;
}
__device__ __forceinline__ uint32_t to_tf32(float v) {
    uint32_t u; asm("cvt.rna.tf32.f32 %0, %1;" : "=r"(u) : "f"(v)); return u;
}

#define MMA_TF32(C, A, B0, B1)                                                  \
    asm("mma.sync.aligned.m16n8k8.row.col.f32.tf32.tf32.f32 "                   \
        "{%0,%1,%2,%3}, {%4,%5,%6,%7}, {%8,%9}, {%0,%1,%2,%3};"                 \
        : "+f"((C)[0]), "+f"((C)[1]), "+f"((C)[2]), "+f"((C)[3])                \
        : "r"((A)[0]), "r"((A)[1]), "r"((A)[2]), "r"((A)[3]), "r"(B0), "r"(B1))

#define CP_ASYNC8(dst, src) \
    asm volatile("cp.async.ca.shared.global [%0], [%1], 8;" :: "r"(dst), "l"(src))
#define CP_COMMIT() asm volatile("cp.async.commit_group;" ::: "memory")
#define CP_WAIT0()  asm volatile("cp.async.wait_group 0;" ::: "memory")
#define PAIR_BAR(id) asm volatile("bar.sync %0, 64;" :: "r"(id) : "memory")

struct LoopState {
    float lwA, lwB;
    ULL ctxA, ctxB;
};

__global__ __launch_bounds__(NTH, 2)
void additive_attn_kernel(const float* __restrict__ dec,
                          const float* __restrict__ enc,     // (S,B,H)
                          const int*   __restrict__ mask,    // (B,S)
                          const float* __restrict__ Wp,
                          const float* __restrict__ We,
                          const float* __restrict__ Ws,
                          float* __restrict__ out)
{
    extern __shared__ __align__(16) char smem[];
    const uint32_t smb = smem_u32(smem);
    float*    ws    = (float*)(smem + OFF_WS);
    float*    ppv   = (float*)(smem + OFF_PPV);
    float*    spart = (float*)(smem + OFF_SPART);
    uint32_t* mbits = (uint32_t*)(smem + OFF_MBITS);
    float*    sl    = (float*)(smem + OFF_SL);
    ULL (*sctx)[25] = (ULL(*)[25])(smem + OFF_SCTX);

    const int b    = blockIdx.x;
    const int tid  = threadIdx.x;
    const int lane = tid & 31;
    const int wid  = tid >> 5;
    const int g    = lane >> 2;
    const int c    = lane & 3;
    const int wr   = wid & 3;      // token block (32 tokens)
    const int wc   = wid >> 2;     // n half
    const int tb   = wr * 32 + wc * 16;   // this warp's 16 context tokens

    // ---- setup: pp, ws ----
    if (tid < 64) {
        float pp = 0.0f;
        if (tid < Hc) {
            #pragma unroll
            for (int k = 0; k < Hc; k++)
                pp = fmaf(Wp[tid * Hc + k], dec[b * Hc + k], pp);
        }
        ppv[tid] = pp;
        ws[tid]  = (tid < Hc) ? Ws[tid] : 0.0f;
    }
    // ---- pack mask row into bitmask (2048 bits = 64 u32) ----
    #pragma unroll
    for (int chunk = 0; chunk < 8; chunk++) {
        int m = mask[(size_t)b * Sc + chunk * 256 + tid];
        unsigned bal = __ballot_sync(0xffffffffu, m != 0);
        if (lane == 0) mbits[chunk * 8 + wid] = bal;
    }
    __syncthreads();

    // ---- build B fragments (fragment-major, tf32) in transient buf1 region ----
    uint32_t* bfrag = (uint32_t*)(smem + OFF_BUF1);
    for (int i = tid; i < 7 * 8 * 32 * 2; i += NTH) {
        int r  = i & 1;
        int ln = (i >> 1) & 31;
        int nb = (i >> 6) & 7;
        int s  = i >> 9;
        int k  = 8 * s + (ln & 3) + 4 * r;
        int n  = nb * 8 + (ln >> 2);
        float v = 0.0f;
        if (n < Hc) {
            if (k < Hc)       v = We[n * Hc + k];
            else if (k == 50) v = ppv[n];
        }
        bfrag[i] = to_tf32(v);
    }
    __syncthreads();

    // ---- hoist B frags + ws to registers ----
    uint2 Breg[7][4];
    #pragma unroll
    for (int s = 0; s < 7; s++)
        #pragma unroll
        for (int nb = 0; nb < 4; nb++)
            Breg[s][nb] = *reinterpret_cast<const uint2*>(
                bfrag + s * 512 + (wc * 4 + nb) * 64 + lane * 2);
    float wsr[4][2];
    #pragma unroll
    for (int nb = 0; nb < 4; nb++) {
        wsr[nb][0] = ws[wc * 32 + nb * 8 + 2 * c];
        wsr[nb][1] = ws[wc * 32 + nb * 8 + 2 * c + 1];
    }
    __syncthreads();   // done reading bfrag; buf1 free

    // ---- init pad cols 50..59 in BOTH buffers ----
    for (int i = tid; i < TT * 10; i += NTH) {
        int t = i / 10, cc = i - 10 * (i / 10);
        float v = (cc == 0) ? 1.0f : 0.0f;          // col 50 = 1.0 (pp lane)
        ((float*)(smem + OFF_BUF0))[t * RS + 50 + cc] = v;
        ((float*)(smem + OFF_BUF1))[t * RS + 50 + cc] = v;
    }

    // ---- staging geometry: lane = 8B chunk (0..24), token = wid + 8i ----
    const float* encb = enc + (size_t)b * Hc;
    const bool st_on = (lane < 25);
    const size_t tok_stride = (size_t)(Bc * Hc);
    const uint32_t d_off = (uint32_t)(wid * RS + 2 * lane) * 4u;
    const size_t  s_off = (size_t)wid * tok_stride + 2 * lane;

    // ---- prologue: prefetch tile 0 into buf0 ----
    if (st_on) {
        const float* s0 = encb + s_off;
        uint32_t d0 = smb + OFF_BUF0 + d_off;
        #pragma unroll
        for (int i = 0; i < 16; i++)
            CP_ASYNC8(d0 + i * (8 * RS * 4), s0 + (size_t)i * 8 * tok_stride);
    }
    CP_COMMIT();

    LoopState st;
    st.lwA = 0.0f; st.lwB = 0.0f; st.ctxA = 0ull; st.ctxB = 0ull;
    const bool skip_nb3 = (wc == 1);   // n 56..63 all have ws == 0
    const int  mshift   = wc << 4;

    auto tile_body = [&](int tt, const float* buf, uint32_t nxt_off) {
        CP_WAIT0();        // own prefetch of tile tt landed
        __syncthreads();   // all warps' tile-tt rows visible; prev buf reads done

        // ---- prefetch tile tt+1 into the other buffer (overlaps MMA) ----
        if (tt + 1 < NTILE && st_on) {
            const float* sn = encb + (size_t)(tt + 1) * TT * tok_stride + s_off;
            uint32_t dn = smb + nxt_off + d_off;
            #pragma unroll
            for (int i = 0; i < 16; i++)
                CP_ASYNC8(dn + i * (8 * RS * 4), sn + (size_t)i * 8 * tok_stride);
        }
        CP_COMMIT();

        const uint32_t mw = mbits[tt * 4 + wr];   // bits for tokens wr*32..+31
        const float* pA0 = buf + (wr * 32 + g) * RS + c;

        // ---- GEMM: warp = 32 tokens x 32 n ----
        float C[2][4][4];
        #pragma unroll
        for (int mt = 0; mt < 2; mt++)
            #pragma unroll
            for (int nb = 0; nb < 4; nb++)
                #pragma unroll
                for (int q = 0; q < 4; q++) C[mt][nb][q] = 0.0f;

        #pragma unroll
        for (int s = 0; s < 7; s++) {
            uint32_t A[2][4];
            #pragma unroll
            for (int mt = 0; mt < 2; mt++) {
                const float* p = pA0 + mt * (16 * RS) + 8 * s;
                A[mt][0] = __float_as_uint(p[0]);
                A[mt][1] = __float_as_uint(p[8 * RS]);
                A[mt][2] = __float_as_uint(p[4]);
                A[mt][3] = __float_as_uint(p[8 * RS + 4]);
            }
            #pragma unroll
            for (int nb = 0; nb < 4; nb++) {
                if (nb == 3 && skip_nb3) continue;
                MMA_TF32(C[0][nb], A[0], Breg[s][nb].x, Breg[s][nb].y);
                MMA_TF32(C[1][nb], A[1], Breg[s][nb].x, Breg[s][nb].y);
            }
        }

        // ---- epilogue: part = sum_n ws[n] * tanh(D) ----
        float part[4] = {0.0f, 0.0f, 0.0f, 0.0f};
        #pragma unroll
        for (int mt = 0; mt < 2; mt++)
            #pragma unroll
            for (int nb = 0; nb < 4; nb++) {
                if (nb == 3 && skip_nb3) continue;
                #pragma unroll
                for (int hi = 0; hi < 2; hi++) {
                    part[mt*2+hi] = fmaf(wsr[nb][0], fast_tanh(C[mt][nb][hi*2]),   part[mt*2+hi]);
                    part[mt*2+hi] = fmaf(wsr[nb][1], fast_tanh(C[mt][nb][hi*2+1]), part[mt*2+hi]);
                }
            }
        #pragma unroll
        for (int q = 0; q < 4; q++) {
            part[q] += __shfl_xor_sync(0xffffffffu, part[q], 1);
            part[q] += __shfl_xor_sync(0xffffffffu, part[q], 2);
        }
        if (c == 0) {
            #pragma unroll
            for (int mt = 0; mt < 2; mt++)
                #pragma unroll
                for (int hi = 0; hi < 2; hi++)
                    spart[wc * TT + wr * 32 + mt * 16 + hi * 8 + g] = part[mt*2+hi];
        }
        PAIR_BAR(wr + 1);   // pair-scoped: producers == consumers for block wr

        // ---- exp in-lane (lane<16 holds token tb+lane), then context ----
        float pv = 0.0f;
        if (lane < 16) {
            int t = tb + lane;
            float sc = spart[t] + spart[TT + t];
            int mk = (mw >> (mshift + lane)) & 1;
            pv = mk ? fast_ex2(sc * L2E) : 0.0f;
        }
        const float* crow = buf + tb * RS + 2 * lane;
        #pragma unroll 2
        for (int r = 0; r < 16; r += 2) {
            float p0 = __shfl_sync(0xffffffffu, pv, r);
            float p1 = __shfl_sync(0xffffffffu, pv, r + 1);
            st.lwA += p0;
            st.lwB += p1;
            if (lane < 25) {
                ULL e0 = *reinterpret_cast<const ULL*>(crow + r * RS);
                ULL e1 = *reinterpret_cast<const ULL*>(crow + (r + 1) * RS);
                FMA2(st.ctxA, pack2(p0, p0), e0);
                FMA2(st.ctxB, pack2(p1, p1), e1);
            }
        }
    };

    #pragma unroll 1
    for (int tt = 0; tt < NTILE; tt += 2) {
        tile_body(tt,     (const float*)(smem + OFF_BUF0), OFF_BUF1);
        tile_body(tt + 1, (const float*)(smem + OFF_BUF1), OFF_BUF0);
    }

    // ---- finalize ----
    ULL   ctx2 = add2(st.ctxA, st.ctxB);
    float lw   = st.lwA + st.lwB;
    if (lane == 0) sl[wid] = lw;
    if (lane < 25) sctx[wid][lane] = ctx2;
    __syncthreads();
    if (tid < 25) {
        float sx = 0.0f, sy = 0.0f, lt = 0.0f;
        #pragma unroll
        for (int i = 0; i < 8; i++) {
            float x, y; unpack2(sctx[i][tid], x, y);
            sx += x; sy += y; lt += sl[i];
        }
        float inv = 1.0f / lt;
        float2 o; o.x = sx * inv; o.y = sy * inv;
        *reinterpret_cast<float2*>(out + (size_t)b * Hc + 2 * tid) = o;
    }
}

extern "C" void kernel_launch(void* const* d_in, const int* in_sizes, int n_in,
                              void* d_out, int out_size) {
    const float* dec  = (const float*)d_in[0];
    const float* enc  = (const float*)d_in[1];
    const int*   mask = (const int*)  d_in[2];
    const float* Wp   = (const float*)d_in[3];
    const float* We   = (const float*)d_in[4];
    const float* Ws   = (const float*)d_in[5];
    float* out = (float*)d_out;

    cudaFuncSetAttribute(additive_attn_kernel,
                         cudaFuncAttributeMaxDynamicSharedMemorySize, SMEM_BYTES);
    additive_attn_kernel<<<Bc, NTH, SMEM_BYTES>>>(dec, enc, mask, Wp, We, Ws, out);
}

// round 14
// speedup vs baseline: 1.0171x; 1.0171x over previous
#include <cuda_runtime.h>
#include <math_constants.h>
#include <cstdint>

typedef unsigned long long ULL;

#define Bc 1024
#define Sc 2048
#define Hc 50
#define TT 128
#define NTILE 16
#define NTH 256
#define RS 60
#define L2E 1.4426950408889634f

// ---- dynamic SMEM layout (bytes), 96384/CTA -> 2 CTAs/SM ----
#define OFF_BUF0  0                // float[128*60] 30720
#define OFF_BUF1  30720            // (transient bfrag home at setup)
#define OFF_BUF2  61440
#define OFF_WS    92160            // float[64]       256
#define OFF_SPART 92416            // float[2][256]  2048
#define OFF_PPV   OFF_SPART        // overlay: setup only
#define OFF_MBITS 94464            // u32[64]         256
#define OFF_SL    94720            // float[8]         32
#define OFF_SCTX  94752            // ULL[8][25]     1600
#define SMEM_BYTES 96384

__device__ __forceinline__ uint32_t smem_u32(const void* p) {
    uint32_t a;
    asm("{ .reg .u64 t; cvta.to.shared.u64 t, %1; cvt.u32.u64 %0, t; }" : "=r"(a) : "l"(p));
    return a;
}
__device__ __forceinline__ float fast_ex2(float x) {
    float r; asm("ex2.approx.f32 %0, %1;" : "=f"(r) : "f"(x)); return r;
}
__device__ __forceinline__ float fast_tanh(float x) {
    float r; asm("tanh.approx.f32 %0, %1;" : "=f"(r) : "f"(x)); return r;
}
__device__ __forceinline__ ULL pack2(float lo, float hi) {
    ULL r; asm("mov.b64 %0, {%1, %2};" : "=l"(r) : "f"(lo), "f"(hi)); return r;
}
__device__ __forceinline__ void unpack2(ULL v, float& lo, float& hi) {
    asm("mov.b64 {%0, %1}, %2;" : "=f"(lo), "=f"(hi) : "l"(v));
}
#define FMA2(d, a, b) asm("fma.rn.f32x2 %0, %1, %2, %0;" : "+l"(d) : "l"(a), "l"(b))
__device__ __forceinline__ ULL add2(ULL a, ULL b) {
    ULL r; asm("add.rn.f32x2 %0, %1, %2;" : "=l"(r) : "l"(a), "l"(b)); return r;
}
__device__ __forceinline__ uint32_t to_tf32(float v) {
    uint32_t u; asm("cvt.rna.tf32.f32 %0, %1;" : "=r"(u) : "f"(v)); return u;
}

#define MMA_TF32(C, A, B0, B1)                                                  \
    asm("mma.sync.aligned.m16n8k8.row.col.f32.tf32.tf32.f32 "                   \
        "{%0,%1,%2,%3}, {%4,%5,%6,%7}, {%8,%9}, {%0,%1,%2,%3};"                 \
        : "+f"((C)[0]), "+f"((C)[1]), "+f"((C)[2]), "+f"((C)[3])                \
        : "r"((A)[0]), "r"((A)[1]), "r"((A)[2]), "r"((A)[3]), "r"(B0), "r"(B1))

#define CP_ASYNC8(dst, src) \
    asm volatile("cp.async.ca.shared.global [%0], [%1], 8;" :: "r"(dst), "l"(src))
#define CP_COMMIT() asm volatile("cp.async.commit_group;" ::: "memory")
#define CP_WAIT1()  asm volatile("cp.async.wait_group 1;" ::: "memory")

__global__ __launch_bounds__(NTH, 2)
void additive_attn_kernel(const float* __restrict__ dec,
                          const float* __restrict__ enc,     // (S,B,H)
                          const int*   __restrict__ mask,    // (B,S)
                          const float* __restrict__ Wp,
                          const float* __restrict__ We,
                          const float* __restrict__ Ws,
                          float* __restrict__ out)
{
    extern __shared__ __align__(16) char smem[];
    const uint32_t smb = smem_u32(smem);
    float*    ws    = (float*)(smem + OFF_WS);
    float*    ppv   = (float*)(smem + OFF_PPV);
    float*    spart = (float*)(smem + OFF_SPART);   // [2][256]
    uint32_t* mbits = (uint32_t*)(smem + OFF_MBITS);
    float*    sl    = (float*)(smem + OFF_SL);
    ULL (*sctx)[25] = (ULL(*)[25])(smem + OFF_SCTX);

    const int b    = blockIdx.x;
    const int tid  = threadIdx.x;
    const int lane = tid & 31;
    const int wid  = tid >> 5;
    const int g    = lane >> 2;
    const int c    = lane & 3;
    const int wr   = wid & 3;      // token block for GEMM (32 tokens)
    const int wc   = wid >> 2;     // n half

    // ---- setup: pp, ws ----
    if (tid < 64) {
        float pp = 0.0f;
        if (tid < Hc) {
            #pragma unroll
            for (int k = 0; k < Hc; k++)
                pp = fmaf(Wp[tid * Hc + k], dec[b * Hc + k], pp);
        }
        ppv[tid] = pp;
        ws[tid]  = (tid < Hc) ? Ws[tid] : 0.0f;
    }
    // ---- pack mask bits warp-major: word tt*4+(w>>1), bit (w&1)*16 + r for token w+8r ----
    #pragma unroll
    for (int chunk = 0; chunk < 8; chunk++) {
        int token = chunk * 256 + ((wid >> 2) << 7)
                  + 2 * (wid & 3) + (lane >> 4) + ((lane & 15) << 3);
        int m = mask[(size_t)b * Sc + token];
        unsigned bal = __ballot_sync(0xffffffffu, m != 0);
        if (lane == 0) mbits[chunk * 8 + wid] = bal;
    }
    __syncthreads();

    // ---- build B fragments (fragment-major, tf32) in transient buf1 region ----
    uint32_t* bfrag = (uint32_t*)(smem + OFF_BUF1);
    for (int i = tid; i < 7 * 8 * 32 * 2; i += NTH) {
        int r  = i & 1;
        int ln = (i >> 1) & 31;
        int nb = (i >> 6) & 7;
        int s  = i >> 9;
        int k  = 8 * s + (ln & 3) + 4 * r;
        int n  = nb * 8 + (ln >> 2);
        float v = 0.0f;
        if (n < Hc) {
            if (k < Hc)       v = We[n * Hc + k];
            else if (k == 50) v = ppv[n];
        }
        bfrag[i] = to_tf32(v);
    }
    __syncthreads();

    // ---- hoist B frags + ws to registers ----
    uint2 Breg[7][4];
    #pragma unroll
    for (int s = 0; s < 7; s++)
        #pragma unroll
        for (int nb = 0; nb < 4; nb++)
            Breg[s][nb] = *reinterpret_cast<const uint2*>(
                bfrag + s * 512 + (wc * 4 + nb) * 64 + lane * 2);
    float wsr[4][2];
    #pragma unroll
    for (int nb = 0; nb < 4; nb++) {
        wsr[nb][0] = ws[wc * 32 + nb * 8 + 2 * c];
        wsr[nb][1] = ws[wc * 32 + nb * 8 + 2 * c + 1];
    }
    __syncthreads();   // bfrag consumed; buf1 free

    // ---- init pad cols 50..59 in ALL buffers ----
    for (int i = tid; i < TT * 10; i += NTH) {
        int t = i / 10, cc = i - 10 * (i / 10);
        float v = (cc == 0) ? 1.0f : 0.0f;          // col 50 = 1.0 (pp lane)
        ((float*)(smem + OFF_BUF0))[t * RS + 50 + cc] = v;
        ((float*)(smem + OFF_BUF1))[t * RS + 50 + cc] = v;
        ((float*)(smem + OFF_BUF2))[t * RS + 50 + cc] = v;
    }

    // ---- staging geometry: lane = 8B chunk (0..24), rows {wid + 8i} ----
    const float* encb = enc + (size_t)b * Hc;
    const bool st_on = (lane < 25);
    const size_t tok_stride = (size_t)(Bc * Hc);
    const uint32_t d_off = (uint32_t)(wid * RS + 2 * lane) * 4u;
    const size_t  s_off = (size_t)wid * tok_stride + 2 * lane;

    // ---- prologue: prefetch tiles 0 (buf0) and 1 (buf1) ----
    if (st_on) {
        const float* s0 = encb + s_off;
        #pragma unroll
        for (int i = 0; i < 16; i++)
            CP_ASYNC8(smb + OFF_BUF0 + d_off + i * (8 * RS * 4),
                      s0 + (size_t)i * 8 * tok_stride);
    }
    CP_COMMIT();
    if (st_on) {
        const float* s1 = encb + (size_t)TT * tok_stride + s_off;
        #pragma unroll
        for (int i = 0; i < 16; i++)
            CP_ASYNC8(smb + OFF_BUF1 + d_off + i * (8 * RS * 4),
                      s1 + (size_t)i * 8 * tok_stride);
    }
    CP_COMMIT();

    float lwA = 0.0f, lwB = 0.0f;
    ULL ctxA = 0ull, ctxB = 0ull;
    const bool skip_nb3 = (wc == 1);   // n 56..63 all have ws == 0
    const int  msh      = (wid & 1) << 4;

    uint32_t oCur = OFF_BUF0, oNxt = OFF_BUF1, oTgt = OFF_BUF2;  // oTgt=(tt-1)%3

    #pragma unroll 1
    for (int tt = 0; tt < NTILE; tt++) {
        CP_WAIT1();        // own prefetch of tile tt landed (group tt+1 may fly)
        __syncthreads();   // staging(tt) + spart(tt-1) visible; GEMM(tt-1) done

        // ---- exp for scores(tt-1): lane r holds p for token wid+8r ----
        float pv = 0.0f;
        if (tt > 0 && lane < 16) {
            uint32_t mw = mbits[(tt - 1) * 4 + (wid >> 1)];
            int t = wid + (lane << 3);
            const float* sp = spart + ((tt - 1) & 1) * 256;
            float sc = sp[t] + sp[128 + t];
            int mk = (mw >> (msh + lane)) & 1;
            pv = mk ? fast_ex2(sc * L2E) : 0.0f;
        }

        const float* buf = (const float*)(smem + oCur);
        const float* pA0 = buf + (wr * 32 + g) * RS + c;

        // ---- GEMM(tt): warp = 32 tokens x 32 n ----
        float C[2][4][4];
        #pragma unroll
        for (int mt = 0; mt < 2; mt++)
            #pragma unroll
            for (int nb = 0; nb < 4; nb++)
                #pragma unroll
                for (int q = 0; q < 4; q++) C[mt][nb][q] = 0.0f;

        #pragma unroll
        for (int s = 0; s < 7; s++) {
            uint32_t A[2][4];
            #pragma unroll
            for (int mt = 0; mt < 2; mt++) {
                const float* p = pA0 + mt * (16 * RS) + 8 * s;
                A[mt][0] = __float_as_uint(p[0]);
                A[mt][1] = __float_as_uint(p[8 * RS]);
                A[mt][2] = __float_as_uint(p[4]);
                A[mt][3] = __float_as_uint(p[8 * RS + 4]);
            }
            #pragma unroll
            for (int nb = 0; nb < 4; nb++) {
                if (nb == 3 && skip_nb3) continue;
                MMA_TF32(C[0][nb], A[0], Breg[s][nb].x, Breg[s][nb].y);
                MMA_TF32(C[1][nb], A[1], Breg[s][nb].x, Breg[s][nb].y);
            }
        }

        // ---- epilogue(tt): part = sum_n ws[n] * tanh(D) -> spart[tt&1] ----
        float part[4] = {0.0f, 0.0f, 0.0f, 0.0f};
        #pragma unroll
        for (int mt = 0; mt < 2; mt++)
            #pragma unroll
            for (int nb = 0; nb < 4; nb++) {
                if (nb == 3 && skip_nb3) continue;
                #pragma unroll
                for (int hi = 0; hi < 2; hi++) {
                    part[mt*2+hi] = fmaf(wsr[nb][0], fast_tanh(C[mt][nb][hi*2]),   part[mt*2+hi]);
                    part[mt*2+hi] = fmaf(wsr[nb][1], fast_tanh(C[mt][nb][hi*2+1]), part[mt*2+hi]);
                }
            }
        #pragma unroll
        for (int q = 0; q < 4; q++) {
            part[q] += __shfl_xor_sync(0xffffffffu, part[q], 1);
            part[q] += __shfl_xor_sync(0xffffffffu, part[q], 2);
        }
        if (c == 0) {
            float* spw = spart + (tt & 1) * 256;
            #pragma unroll
            for (int mt = 0; mt < 2; mt++)
                #pragma unroll
                for (int hi = 0; hi < 2; hi++)
                    spw[wc * TT + wr * 32 + mt * 16 + hi * 8 + g] = part[mt*2+hi];
        }

        // ---- context(tt-1) on buf(tt-1): rows {wid+8r}, self-owned ----
        const float* crow = (const float*)(smem + oTgt) + wid * RS + 2 * lane;
        if (tt > 0) {
            #pragma unroll 2
            for (int r = 0; r < 16; r += 2) {
                float p0 = __shfl_sync(0xffffffffu, pv, r);
                float p1 = __shfl_sync(0xffffffffu, pv, r + 1);
                lwA += p0;
                lwB += p1;
                if (lane < 25) {
                    ULL e0 = *reinterpret_cast<const ULL*>(crow + r * (8 * RS));
                    ULL e1 = *reinterpret_cast<const ULL*>(crow + (r + 1) * (8 * RS));
                    FMA2(ctxA, pack2(p0, p0), e0);
                    FMA2(ctxB, pack2(p1, p1), e1);
                }
            }
        }

        // ---- prefetch(tt+2) into buf(tt-1): same rows this warp just read ----
        if (tt < NTILE - 2 && st_on) {
            const float* sn = encb + (size_t)(tt + 2) * TT * tok_stride + s_off;
            uint32_t dn = smb + oTgt + d_off;
            #pragma unroll
            for (int i = 0; i < 16; i++)
                CP_ASYNC8(dn + i * (8 * RS * 4), sn + (size_t)i * 8 * tok_stride);
        }
        CP_COMMIT();

        // rotate buffers: (cur, nxt, tgt) <- (nxt, tgt, cur)
        uint32_t t0 = oCur; oCur = oNxt; oNxt = oTgt; oTgt = t0;
    }

    // ---- trailing context for tile 15 (in oTgt after final rotation) ----
    __syncthreads();
    {
        float pv = 0.0f;
        if (lane < 16) {
            uint32_t mw = mbits[15 * 4 + (wid >> 1)];
            int t = wid + (lane << 3);
            const float* sp = spart + (15 & 1) * 256;
            float sc = sp[t] + sp[128 + t];
            int mk = (mw >> (msh + lane)) & 1;
            pv = mk ? fast_ex2(sc * L2E) : 0.0f;
        }
        const float* crow = (const float*)(smem + oTgt) + wid * RS + 2 * lane;
        #pragma unroll 2
        for (int r = 0; r < 16; r += 2) {
            float p0 = __shfl_sync(0xffffffffu, pv, r);
            float p1 = __shfl_sync(0xffffffffu, pv, r + 1);
            lwA += p0;
            lwB += p1;
            if (lane < 25) {
                ULL e0 = *reinterpret_cast<const ULL*>(crow + r * (8 * RS));
                ULL e1 = *reinterpret_cast<const ULL*>(crow + (r + 1) * (8 * RS));
                FMA2(ctxA, pack2(p0, p0), e0);
                FMA2(ctxB, pack2(p1, p1), e1);
            }
        }
    }

    // ---- finalize ----
    ULL   ctx2 = add2(ctxA, ctxB);
    float lw   = lwA + lwB;
    __syncthreads();
    if (lane == 0) sl[wid] = lw;
    if (lane < 25) sctx[wid][lane] = ctx2;
    __syncthreads();
    if (tid < 25) {
        float sx = 0.0f, sy = 0.0f, lt = 0.0f;
        #pragma unroll
        for (int i = 0; i < 8; i++) {
            float x, y; unpack2(sctx[i][tid], x, y);
            sx += x; sy += y; lt += sl[i];
        }
        float inv = 1.0f / lt;
        float2 o; o.x = sx * inv; o.y = sy * inv;
        *reinterpret_cast<float2*>(out + (size_t)b * Hc + 2 * tid) = o;
    }
}

extern "C" void kernel_launch(void* const* d_in, const int* in_sizes, int n_in,
                              void* d_out, int out_size) {
    const float* dec  = (const float*)d_in[0];
    const float* enc  = (const float*)d_in[1];
    const int*   mask = (const int*)  d_in[2];
    const float* Wp   = (const float*)d_in[3];
    const float* We   = (const float*)d_in[4];
    const float* Ws   = (const float*)d_in[5];
    float* out = (float*)d_out;

    cudaFuncSetAttribute(additive_attn_kernel,
                         cudaFuncAttributeMaxDynamicSharedMemorySize, SMEM_BYTES);
    additive_attn_kernel<<<Bc, NTH, SMEM_BYTES>>>(dec, enc, mask, Wp, We, Ws, out);
}

// round 15
// speedup vs baseline: 1.1403x; 1.1211x over previous
#include <cuda_runtime.h>
#include <math_constants.h>
#include <cstdint>

typedef unsigned long long ULL;

#define Bc 1024
#define Sc 2048
#define Hc 50
#define TT 64
#define NTILE 32
#define NTH 128
#define RS 60
#define L2E 1.4426950408889634f

// ---- dynamic SMEM layout (bytes), 32608/CTA -> 4 CTAs/SM ----
#define OFF_BUF0  0                // float[64*60] 15360
#define OFF_BUF1  15360            // float[64*60] 15360 (transient bfrag at setup)
#define OFF_WS    30720            // float[64]      256
#define OFF_SPART 30976            // float[2*64]    512
#define OFF_PPV   OFF_SPART        // overlay: setup only
#define OFF_MBITS 31488            // u32[64]        256
#define OFF_SL    31744            // float[4]        32
#define OFF_SCTX  31776            // ULL[4][25]     800
#define SMEM_BYTES 32608

__device__ __forceinline__ uint32_t smem_u32(const void* p) {
    uint32_t a;
    asm("{ .reg .u64 t; cvta.to.shared.u64 t, %1; cvt.u32.u64 %0, t; }" : "=r"(a) : "l"(p));
    return a;
}
__device__ __forceinline__ float fast_ex2(float x) {
    float r; asm("ex2.approx.f32 %0, %1;" : "=f"(r) : "f"(x)); return r;
}
__device__ __forceinline__ float fast_tanh(float x) {
    float r; asm("tanh.approx.f32 %0, %1;" : "=f"(r) : "f"(x)); return r;
}
__device__ __forceinline__ ULL pack2(float lo, float hi) {
    ULL r; asm("mov.b64 %0, {%1, %2};" : "=l"(r) : "f"(lo), "f"(hi)); return r;
}
__device__ __forceinline__ void unpack2(ULL v, float& lo, float& hi) {
    asm("mov.b64 {%0, %1}, %2;" : "=f"(lo), "=f"(hi) : "l"(v));
}
#define FMA2(d, a, b) asm("fma.rn.f32x2 %0, %1, %2, %0;" : "+l"(d) : "l"(a), "l"(b))
__device__ __forceinline__ ULL add2(ULL a, ULL b) {
    ULL r; asm("add.rn.f32x2 %0, %1, %2;" : "=l"(r) : "l"(a), "l"(b)); return r;
}
__device__ __forceinline__ uint32_t to_tf32(float v) {
    uint32_t u; asm("cvt.rna.tf32.f32 %0, %1;" : "=r"(u) : "f"(v)); return u;
}

#define MMA_TF32(C, A, B0, B1)                                                  \
    asm("mma.sync.aligned.m16n8k8.row.col.f32.tf32.tf32.f32 "                   \
        "{%0,%1,%2,%3}, {%4,%5,%6,%7}, {%8,%9}, {%0,%1,%2,%3};"                 \
        : "+f"((C)[0]), "+f"((C)[1]), "+f"((C)[2]), "+f"((C)[3])                \
        : "r"((A)[0]), "r"((A)[1]), "r"((A)[2]), "r"((A)[3]), "r"(B0), "r"(B1))

#define CP_ASYNC8(dst, src) \
    asm volatile("cp.async.ca.shared.global [%0], [%1], 8;" :: "r"(dst), "l"(src))
#define CP_COMMIT() asm volatile("cp.async.commit_group;" ::: "memory")
#define CP_WAIT0()  asm volatile("cp.async.wait_group 0;" ::: "memory")

__global__ __launch_bounds__(NTH, 4)
void additive_attn_kernel(const float* __restrict__ dec,
                          const float* __restrict__ enc,     // (S,B,H)
                          const int*   __restrict__ mask,    // (B,S)
                          const float* __restrict__ Wp,
                          const float* __restrict__ We,
                          const float* __restrict__ Ws,
                          float* __restrict__ out)
{
    extern __shared__ __align__(16) char smem[];
    const uint32_t smb = smem_u32(smem);
    float*    ws    = (float*)(smem + OFF_WS);
    float*    ppv   = (float*)(smem + OFF_PPV);
    float*    spart = (float*)(smem + OFF_SPART);
    uint32_t* mbits = (uint32_t*)(smem + OFF_MBITS);
    float*    sl    = (float*)(smem + OFF_SL);
    ULL (*sctx)[25] = (ULL(*)[25])(smem + OFF_SCTX);

    const int b    = blockIdx.x;
    const int tid  = threadIdx.x;
    const int lane = tid & 31;
    const int wid  = tid >> 5;     // 0..3
    const int g    = lane >> 2;
    const int c    = lane & 3;
    const int wr   = wid & 1;      // token block (32 tokens)
    const int wc   = wid >> 1;     // n half

    // ---- setup: pp, ws ----
    if (tid < 64) {
        float pp = 0.0f;
        if (tid < Hc) {
            #pragma unroll
            for (int k = 0; k < Hc; k++)
                pp = fmaf(Wp[tid * Hc + k], dec[b * Hc + k], pp);
        }
        ppv[tid] = pp;
        ws[tid]  = (tid < Hc) ? Ws[tid] : 0.0f;
    }
    // ---- pack mask row into bitmask (2048 bits = 64 u32, natural order) ----
    #pragma unroll
    for (int chunk = 0; chunk < 16; chunk++) {
        int m = mask[(size_t)b * Sc + chunk * 128 + tid];
        unsigned bal = __ballot_sync(0xffffffffu, m != 0);
        if (lane == 0) mbits[chunk * 4 + wid] = bal;
    }
    __syncthreads();

    // ---- build B fragments (fragment-major, tf32) in transient buf1 region ----
    uint32_t* bfrag = (uint32_t*)(smem + OFF_BUF1);
    for (int i = tid; i < 7 * 8 * 32 * 2; i += NTH) {
        int r  = i & 1;
        int ln = (i >> 1) & 31;
        int nb = (i >> 6) & 7;
        int s  = i >> 9;
        int k  = 8 * s + (ln & 3) + 4 * r;
        int n  = nb * 8 + (ln >> 2);
        float v = 0.0f;
        if (n < Hc) {
            if (k < Hc)       v = We[n * Hc + k];
            else if (k == 50) v = ppv[n];
        }
        bfrag[i] = to_tf32(v);
    }
    __syncthreads();

    // ---- hoist B frags + ws to registers ----
    uint2 Breg[7][4];
    #pragma unroll
    for (int s = 0; s < 7; s++)
        #pragma unroll
        for (int nb = 0; nb < 4; nb++)
            Breg[s][nb] = *reinterpret_cast<const uint2*>(
                bfrag + s * 512 + (wc * 4 + nb) * 64 + lane * 2);
    float wsr[4][2];
    #pragma unroll
    for (int nb = 0; nb < 4; nb++) {
        wsr[nb][0] = ws[wc * 32 + nb * 8 + 2 * c];
        wsr[nb][1] = ws[wc * 32 + nb * 8 + 2 * c + 1];
    }
    __syncthreads();   // done reading bfrag; buf1 free

    // ---- init pad cols 50..59 in BOTH buffers ----
    for (int i = tid; i < TT * 10; i += NTH) {
        int t = i / 10, cc = i - 10 * (i / 10);
        float v = (cc == 0) ? 1.0f : 0.0f;          // col 50 = 1.0 (pp lane)
        ((float*)(smem + OFF_BUF0))[t * RS + 50 + cc] = v;
        ((float*)(smem + OFF_BUF1))[t * RS + 50 + cc] = v;
    }

    // ---- staging geometry: lane = 8B chunk (0..24), token = wid + 4i ----
    const float* encb = enc + (size_t)b * Hc;
    const bool st_on = (lane < 25);
    const size_t tok_stride = (size_t)(Bc * Hc);
    const uint32_t d_off = (uint32_t)(wid * RS + 2 * lane) * 4u;
    const size_t  s_off = (size_t)wid * tok_stride + 2 * lane;

    // ---- prologue: prefetch tile 0 into buf0 ----
    if (st_on) {
        const float* s0 = encb + s_off;
        uint32_t d0 = smb + OFF_BUF0 + d_off;
        #pragma unroll
        for (int i = 0; i < 16; i++)
            CP_ASYNC8(d0 + i * (4 * RS * 4), s0 + (size_t)i * 4 * tok_stride);
    }
    CP_COMMIT();

    float lwA = 0.0f, lwB = 0.0f;
    ULL ctxA = 0ull, ctxB = 0ull;
    const bool skip_nb3 = (wc == 1);   // n 56..63 all have ws == 0
    const int  mshift   = (wid & 1) << 4;

    #pragma unroll 1
    for (int tt = 0; tt < NTILE; tt++) {
        const int par = tt & 1;

        CP_WAIT0();        // own prefetch of tile tt landed
        __syncthreads();   // all warps' tile-tt rows visible; prev buf reads done

        // ---- prefetch tile tt+1 into the other buffer (overlaps MMA below) ----
        if (tt + 1 < NTILE && st_on) {
            const float* sn = encb + (size_t)(tt + 1) * TT * tok_stride + s_off;
            uint32_t dn = smb + (par ? OFF_BUF0 : OFF_BUF1) + d_off;
            #pragma unroll
            for (int i = 0; i < 16; i++)
                CP_ASYNC8(dn + i * (4 * RS * 4), sn + (size_t)i * 4 * tok_stride);
        }
        CP_COMMIT();

        // mask bits for this warp's 16 context tokens (1 LDS broadcast)
        const uint32_t mw = mbits[tt * 2 + (wid >> 1)];

        const float* buf = (const float*)(smem + (par ? OFF_BUF1 : OFF_BUF0));
        const float* pA0 = buf + (wr * 32 + g) * RS + c;

        // ---- GEMM: warp = 32 tokens x 32 n ----
        float C[2][4][4];
        #pragma unroll
        for (int mt = 0; mt < 2; mt++)
            #pragma unroll
            for (int nb = 0; nb < 4; nb++)
                #pragma unroll
                for (int q = 0; q < 4; q++) C[mt][nb][q] = 0.0f;

        #pragma unroll
        for (int s = 0; s < 7; s++) {
            uint32_t A[2][4];
            #pragma unroll
            for (int mt = 0; mt < 2; mt++) {
                const float* p = pA0 + mt * (16 * RS) + 8 * s;
                A[mt][0] = __float_as_uint(p[0]);
                A[mt][1] = __float_as_uint(p[8 * RS]);
                A[mt][2] = __float_as_uint(p[4]);
                A[mt][3] = __float_as_uint(p[8 * RS + 4]);
            }
            #pragma unroll
            for (int nb = 0; nb < 4; nb++) {
                if (nb == 3 && skip_nb3) continue;
                MMA_TF32(C[0][nb], A[0], Breg[s][nb].x, Breg[s][nb].y);
                MMA_TF32(C[1][nb], A[1], Breg[s][nb].x, Breg[s][nb].y);
            }
        }

        // ---- epilogue: part = sum_n ws[n] * tanh(D) ----
        float part[4] = {0.0f, 0.0f, 0.0f, 0.0f};
        #pragma unroll
        for (int mt = 0; mt < 2; mt++)
            #pragma unroll
            for (int nb = 0; nb < 4; nb++) {
                if (nb == 3 && skip_nb3) continue;
                #pragma unroll
                for (int hi = 0; hi < 2; hi++) {
                    part[mt*2+hi] = fmaf(wsr[nb][0], fast_tanh(C[mt][nb][hi*2]),   part[mt*2+hi]);
                    part[mt*2+hi] = fmaf(wsr[nb][1], fast_tanh(C[mt][nb][hi*2+1]), part[mt*2+hi]);
                }
            }
        #pragma unroll
        for (int q = 0; q < 4; q++) {
            part[q] += __shfl_xor_sync(0xffffffffu, part[q], 1);
            part[q] += __shfl_xor_sync(0xffffffffu, part[q], 2);
        }
        if (c == 0) {
            #pragma unroll
            for (int mt = 0; mt < 2; mt++)
                #pragma unroll
                for (int hi = 0; hi < 2; hi++)
                    spart[wc * TT + wr * 32 + mt * 16 + hi * 8 + g] = part[mt*2+hi];
        }
        __syncthreads();   // score partials visible

        // ---- exp in-lane (lane<16 holds token wid*16+lane), then context ----
        float pv = 0.0f;
        if (lane < 16) {
            int t = (wid << 4) + lane;
            float sc = spart[t] + spart[TT + t];
            int mk = (mw >> (mshift + lane)) & 1;
            pv = mk ? fast_ex2(sc * L2E) : 0.0f;
        }
        const float* crow = buf + (wid << 4) * RS + 2 * lane;
        #pragma unroll 2
        for (int r = 0; r < 16; r += 2) {
            float p0 = __shfl_sync(0xffffffffu, pv, r);
            float p1 = __shfl_sync(0xffffffffu, pv, r + 1);
            lwA += p0;
            lwB += p1;
            if (lane < 25) {
                ULL e0 = *reinterpret_cast<const ULL*>(crow + r * RS);
                ULL e1 = *reinterpret_cast<const ULL*>(crow + (r + 1) * RS);
                FMA2(ctxA, pack2(p0, p0), e0);
                FMA2(ctxB, pack2(p1, p1), e1);
            }
        }
    }

    // ---- finalize ----
    ULL   ctx2 = add2(ctxA, ctxB);
    float lw   = lwA + lwB;
    if (lane == 0) sl[wid] = lw;
    if (lane < 25) sctx[wid][lane] = ctx2;
    __syncthreads();
    if (tid < 25) {
        float sx = 0.0f, sy = 0.0f, lt = 0.0f;
        #pragma unroll
        for (int i = 0; i < 4; i++) {
            float x, y; unpack2(sctx[i][tid], x, y);
            sx += x; sy += y; lt += sl[i];
        }
        float inv = 1.0f / lt;
        float2 o; o.x = sx * inv; o.y = sy * inv;
        *reinterpret_cast<float2*>(out + (size_t)b * Hc + 2 * tid) = o;
    }
}

extern "C" void kernel_launch(void* const* d_in, const int* in_sizes, int n_in,
                              void* d_out, int out_size) {
    const float* dec  = (const float*)d_in[0];
    const float* enc  = (const float*)d_in[1];
    const int*   mask = (const int*)  d_in[2];
    const float* Wp   = (const float*)d_in[3];
    const float* We   = (const float*)d_in[4];
    const float* Ws   = (const float*)d_in[5];
    float* out = (float*)d_out;

    cudaFuncSetAttribute(additive_attn_kernel,
                         cudaFuncAttributeMaxDynamicSharedMemorySize, SMEM_BYTES);
    additive_attn_kernel<<<Bc, NTH, SMEM_BYTES>>>(dec, enc, mask, Wp, We, Ws, out);
}

// round 16
// speedup vs baseline: 1.1665x; 1.0230x over previous
#include <cuda_runtime.h>
#include <math_constants.h>
#include <cstdint>

typedef unsigned long long ULL;

#define Bc 1024
#define Sc 2048
#define Hc 50
#define TT 64
#define NTILE 32
#define NTH 128
#define RS 60
#define L2E 1.4426950408889634f

// ---- dynamic SMEM layout (bytes), 32608/CTA -> 4 CTAs/SM ----
#define OFF_BUF0  0                // float[64*60] 15360
#define OFF_BUF1  15360            // float[64*60] 15360 (transient bfrag at setup)
#define OFF_WS    30720            // float[64]      256
#define OFF_SPART 30976            // float[2*64]    512
#define OFF_PPV   OFF_SPART        // overlay: setup only
#define OFF_MBITS 31488            // u32[64]        256
#define OFF_SL    31744            // float[4]        32
#define OFF_SCTX  31776            // ULL[4][25]     800
#define SMEM_BYTES 32608

__device__ __forceinline__ uint32_t smem_u32(const void* p) {
    uint32_t a;
    asm("{ .reg .u64 t; cvta.to.shared.u64 t, %1; cvt.u32.u64 %0, t; }" : "=r"(a) : "l"(p));
    return a;
}
__device__ __forceinline__ float fast_ex2(float x) {
    float r; asm("ex2.approx.f32 %0, %1;" : "=f"(r) : "f"(x)); return r;
}
__device__ __forceinline__ float fast_tanh(float x) {
    float r; asm("tanh.approx.f32 %0, %1;" : "=f"(r) : "f"(x)); return r;
}
__device__ __forceinline__ ULL pack2(float lo, float hi) {
    ULL r; asm("mov.b64 %0, {%1, %2};" : "=l"(r) : "f"(lo), "f"(hi)); return r;
}
__device__ __forceinline__ void unpack2(ULL v, float& lo, float& hi) {
    asm("mov.b64 {%0, %1}, %2;" : "=f"(lo), "=f"(hi) : "l"(v));
}
#define FMA2(d, a, b) asm("fma.rn.f32x2 %0, %1, %2, %0;" : "+l"(d) : "l"(a), "l"(b))
__device__ __forceinline__ ULL add2(ULL a, ULL b) {
    ULL r; asm("add.rn.f32x2 %0, %1, %2;" : "=l"(r) : "l"(a), "l"(b)); return r;
}
__device__ __forceinline__ uint32_t to_tf32(float v) {
    uint32_t u; asm("cvt.rna.tf32.f32 %0, %1;" : "=r"(u) : "f"(v)); return u;
}

#define MMA_TF32(C, A, B0, B1)                                                  \
    asm("mma.sync.aligned.m16n8k8.row.col.f32.tf32.tf32.f32 "                   \
        "{%0,%1,%2,%3}, {%4,%5,%6,%7}, {%8,%9}, {%0,%1,%2,%3};"                 \
        : "+f"((C)[0]), "+f"((C)[1]), "+f"((C)[2]), "+f"((C)[3])                \
        : "r"((A)[0]), "r"((A)[1]), "r"((A)[2]), "r"((A)[3]), "r"(B0), "r"(B1))

#define CP_ASYNC8(dst, src) \
    asm volatile("cp.async.ca.shared.global [%0], [%1], 8;" :: "r"(dst), "l"(src))
#define CP_COMMIT() asm volatile("cp.async.commit_group;" ::: "memory")
#define CP_WAIT0()  asm volatile("cp.async.wait_group 0;" ::: "memory")

// staging: CNT contiguous rows starting at this warp's start row
#define STAGE_ROWS(dst0, src0, CNT) do {                                        \
    _Pragma("unroll")                                                           \
    for (int i = 0; i < (CNT); i++)                                             \
        CP_ASYNC8((dst0) + i * (RS * 4), (src0) + (size_t)i * tok_stride);      \
} while (0)

// context over CNT rows from crow (pairs)
#define CTX_ROWS(CNT) do {                                                      \
    _Pragma("unroll")                                                           \
    for (int r = 0; r < (CNT); r += 2) {                                        \
        float p0 = __shfl_sync(0xffffffffu, pv, r);                             \
        float p1 = __shfl_sync(0xffffffffu, pv, r + 1);                         \
        lwA += p0;                                                              \
        lwB += p1;                                                              \
        if (lane < 25) {                                                        \
            ULL e0 = *reinterpret_cast<const ULL*>(crow + r * RS);              \
            ULL e1 = *reinterpret_cast<const ULL*>(crow + (r + 1) * RS);        \
            FMA2(ctxA, pack2(p0, p0), e0);                                      \
            FMA2(ctxB, pack2(p1, p1), e1);                                      \
        }                                                                       \
    }                                                                           \
} while (0)

__global__ __launch_bounds__(NTH, 4)
void additive_attn_kernel(const float* __restrict__ dec,
                          const float* __restrict__ enc,     // (S,B,H)
                          const int*   __restrict__ mask,    // (B,S)
                          const float* __restrict__ Wp,
                          const float* __restrict__ We,
                          const float* __restrict__ Ws,
                          float* __restrict__ out)
{
    extern __shared__ __align__(16) char smem[];
    const uint32_t smb = smem_u32(smem);
    float*    ws    = (float*)(smem + OFF_WS);
    float*    ppv   = (float*)(smem + OFF_PPV);
    float*    spart = (float*)(smem + OFF_SPART);
    uint32_t* mbits = (uint32_t*)(smem + OFF_MBITS);
    float*    sl    = (float*)(smem + OFF_SL);
    ULL (*sctx)[25] = (ULL(*)[25])(smem + OFF_SCTX);

    const int b    = blockIdx.x;
    const int tid  = threadIdx.x;
    const int lane = tid & 31;
    const int wid  = tid >> 5;     // 0..3
    const int g    = lane >> 2;
    const int c    = lane & 3;
    const int wr   = wid & 1;      // token block (32 tokens)
    const int wc   = wid >> 1;     // n half (0 = heavy: 4 n-blocks; 1 = light: 3)

    // ---- load-balance split: heavy warps 12 ctx/staging rows, light 20 ----
    // wid0 (wr0,wc0): rows  0-11 | wid2 (wr0,wc1): rows 12-31
    // wid1 (wr1,wc0): rows 32-43 | wid3 (wr1,wc1): rows 44-63
    const int rstart = wr * 32 + (wc ? 12 : 0);
    const int msh    = wc ? 12 : 0;

    // ---- setup: pp, ws ----
    if (tid < 64) {
        float pp = 0.0f;
        if (tid < Hc) {
            #pragma unroll
            for (int k = 0; k < Hc; k++)
                pp = fmaf(Wp[tid * Hc + k], dec[b * Hc + k], pp);
        }
        ppv[tid] = pp;
        ws[tid]  = (tid < Hc) ? Ws[tid] : 0.0f;
    }
    // ---- pack mask row into bitmask (2048 bits = 64 u32, natural order) ----
    #pragma unroll
    for (int chunk = 0; chunk < 16; chunk++) {
        int m = mask[(size_t)b * Sc + chunk * 128 + tid];
        unsigned bal = __ballot_sync(0xffffffffu, m != 0);
        if (lane == 0) mbits[chunk * 4 + wid] = bal;
    }
    __syncthreads();

    // ---- build B fragments (fragment-major, tf32) in transient buf1 region ----
    uint32_t* bfrag = (uint32_t*)(smem + OFF_BUF1);
    for (int i = tid; i < 7 * 8 * 32 * 2; i += NTH) {
        int r  = i & 1;
        int ln = (i >> 1) & 31;
        int nb = (i >> 6) & 7;
        int s  = i >> 9;
        int k  = 8 * s + (ln & 3) + 4 * r;
        int n  = nb * 8 + (ln >> 2);
        float v = 0.0f;
        if (n < Hc) {
            if (k < Hc)       v = We[n * Hc + k];
            else if (k == 50) v = ppv[n];
        }
        bfrag[i] = to_tf32(v);
    }
    __syncthreads();

    // ---- hoist B frags + ws to registers ----
    uint2 Breg[7][4];
    #pragma unroll
    for (int s = 0; s < 7; s++)
        #pragma unroll
        for (int nb = 0; nb < 4; nb++)
            Breg[s][nb] = *reinterpret_cast<const uint2*>(
                bfrag + s * 512 + (wc * 4 + nb) * 64 + lane * 2);
    float wsr[4][2];
    #pragma unroll
    for (int nb = 0; nb < 4; nb++) {
        wsr[nb][0] = ws[wc * 32 + nb * 8 + 2 * c];
        wsr[nb][1] = ws[wc * 32 + nb * 8 + 2 * c + 1];
    }
    __syncthreads();   // done reading bfrag; buf1 free

    // ---- init pad cols 50..59 in BOTH buffers ----
    for (int i = tid; i < TT * 10; i += NTH) {
        int t = i / 10, cc = i - 10 * (i / 10);
        float v = (cc == 0) ? 1.0f : 0.0f;          // col 50 = 1.0 (pp lane)
        ((float*)(smem + OFF_BUF0))[t * RS + 50 + cc] = v;
        ((float*)(smem + OFF_BUF1))[t * RS + 50 + cc] = v;
    }

    // ---- staging geometry: lane = 8B chunk (0..24), rows [rstart, rstart+cnt) ----
    const float* encb = enc + (size_t)b * Hc;
    const bool st_on = (lane < 25);
    const size_t tok_stride = (size_t)(Bc * Hc);
    const uint32_t d_off = (uint32_t)(rstart * RS + 2 * lane) * 4u;
    const size_t  s_off = (size_t)rstart * tok_stride + 2 * lane;

    // ---- prologue: prefetch tile 0 into buf0 ----
    if (st_on) {
        const float* s0 = encb + s_off;
        uint32_t d0 = smb + OFF_BUF0 + d_off;
        if (wc == 0) STAGE_ROWS(d0, s0, 12); else STAGE_ROWS(d0, s0, 20);
    }
    CP_COMMIT();

    float lwA = 0.0f, lwB = 0.0f;
    ULL ctxA = 0ull, ctxB = 0ull;
    const bool skip_nb3 = (wc == 1);   // n 56..63 all have ws == 0

    #pragma unroll 1
    for (int tt = 0; tt < NTILE; tt++) {
        const int par = tt & 1;

        CP_WAIT0();        // own prefetch of tile tt landed
        __syncthreads();   // all warps' tile-tt rows visible; prev buf reads done

        // ---- prefetch tile tt+1 into the other buffer (overlaps MMA below) ----
        if (tt + 1 < NTILE && st_on) {
            const float* sn = encb + (size_t)(tt + 1) * TT * tok_stride + s_off;
            uint32_t dn = smb + (par ? OFF_BUF0 : OFF_BUF1) + d_off;
            if (wc == 0) STAGE_ROWS(dn, sn, 12); else STAGE_ROWS(dn, sn, 20);
        }
        CP_COMMIT();

        // mask bits for this warp's context tokens (1 LDS broadcast)
        const uint32_t mw = mbits[tt * 2 + wr];

        const float* buf = (const float*)(smem + (par ? OFF_BUF1 : OFF_BUF0));
        const float* pA0 = buf + (wr * 32 + g) * RS + c;

        // ---- GEMM: warp = 32 tokens x 32 n ----
        float C[2][4][4];
        #pragma unroll
        for (int mt = 0; mt < 2; mt++)
            #pragma unroll
            for (int nb = 0; nb < 4; nb++)
                #pragma unroll
                for (int q = 0; q < 4; q++) C[mt][nb][q] = 0.0f;

        #pragma unroll
        for (int s = 0; s < 7; s++) {
            uint32_t A[2][4];
            #pragma unroll
            for (int mt = 0; mt < 2; mt++) {
                const float* p = pA0 + mt * (16 * RS) + 8 * s;
                A[mt][0] = __float_as_uint(p[0]);
                A[mt][1] = __float_as_uint(p[8 * RS]);
                A[mt][2] = __float_as_uint(p[4]);
                A[mt][3] = __float_as_uint(p[8 * RS + 4]);
            }
            #pragma unroll
            for (int nb = 0; nb < 4; nb++) {
                if (nb == 3 && skip_nb3) continue;
                MMA_TF32(C[0][nb], A[0], Breg[s][nb].x, Breg[s][nb].y);
                MMA_TF32(C[1][nb], A[1], Breg[s][nb].x, Breg[s][nb].y);
            }
        }

        // ---- epilogue: part = sum_n ws[n] * tanh(D) ----
        float part[4] = {0.0f, 0.0f, 0.0f, 0.0f};
        #pragma unroll
        for (int mt = 0; mt < 2; mt++)
            #pragma unroll
            for (int nb = 0; nb < 4; nb++) {
                if (nb == 3 && skip_nb3) continue;
                #pragma unroll
                for (int hi = 0; hi < 2; hi++) {
                    part[mt*2+hi] = fmaf(wsr[nb][0], fast_tanh(C[mt][nb][hi*2]),   part[mt*2+hi]);
                    part[mt*2+hi] = fmaf(wsr[nb][1], fast_tanh(C[mt][nb][hi*2+1]), part[mt*2+hi]);
                }
            }
        #pragma unroll
        for (int q = 0; q < 4; q++) {
            part[q] += __shfl_xor_sync(0xffffffffu, part[q], 1);
            part[q] += __shfl_xor_sync(0xffffffffu, part[q], 2);
        }
        if (c == 0) {
            #pragma unroll
            for (int mt = 0; mt < 2; mt++)
                #pragma unroll
                for (int hi = 0; hi < 2; hi++)
                    spart[wc * TT + wr * 32 + mt * 16 + hi * 8 + g] = part[mt*2+hi];
        }
        __syncthreads();   // score partials visible

        // ---- exp in-lane (lane<cnt holds token rstart+lane), then context ----
        float pv = 0.0f;
        if (lane < (wc ? 20 : 12)) {
            int t = rstart + lane;
            float sc = spart[t] + spart[TT + t];
            int mk = (mw >> (msh + lane)) & 1;
            pv = mk ? fast_ex2(sc * L2E) : 0.0f;
        }
        const float* crow = buf + rstart * RS + 2 * lane;
        if (wc == 0) CTX_ROWS(12); else CTX_ROWS(20);
    }

    // ---- finalize ----
    ULL   ctx2 = add2(ctxA, ctxB);
    float lw   = lwA + lwB;
    if (lane == 0) sl[wid] = lw;
    if (lane < 25) sctx[wid][lane] = ctx2;
    __syncthreads();
    if (tid < 25) {
        float sx = 0.0f, sy = 0.0f, lt = 0.0f;
        #pragma unroll
        for (int i = 0; i < 4; i++) {
            float x, y; unpack2(sctx[i][tid], x, y);
            sx += x; sy += y; lt += sl[i];
        }
        float inv = 1.0f / lt;
        float2 o; o.x = sx * inv; o.y = sy * inv;
        *reinterpret_cast<float2*>(out + (size_t)b * Hc + 2 * tid) = o;
    }
}

extern "C" void kernel_launch(void* const* d_in, const int* in_sizes, int n_in,
                              void* d_out, int out_size) {
    const float* dec  = (const float*)d_in[0];
    const float* enc  = (const float*)d_in[1];
    const int*   mask = (const int*)  d_in[2];
    const float* Wp   = (const float*)d_in[3];
    const float* We   = (const float*)d_in[4];
    const float* Ws   = (const float*)d_in[5];
    float* out = (float*)d_out;

    cudaFuncSetAttribute(additive_attn_kernel,
                         cudaFuncAttributeMaxDynamicSharedMemorySize, SMEM_BYTES);
    additive_attn_kernel<<<Bc, NTH, SMEM_BYTES>>>(dec, enc, mask, Wp, We, Ws, out);
}